// round 16
// baseline (speedup 1.0000x reference)
#include <cuda_runtime.h>
#include <cuda_bf16.h>
#include <cstdint>

#define BATCH 8
#define C1    128
#define C2    256
#define HIN   160
#define HO    80
#define SPIX  6400
#define NPIX  51200
#define K1    1152
#define K3    2304
#define PX    64        // pixel tile per CTA

// -------- scratch (device globals; no runtime allocation) --------
__device__ float g_h  [BATCH*C2*SPIX];   // NCHW: [b][ci][pixel]
__device__ float g_off[BATCH*18*SPIX];   // offsets
__device__ __nv_bfloat16 g_w1h[C2*K1];   // conv1 weights, k=tap*128+ci, hi
__device__ __nv_bfloat16 g_w1l[C2*K1];   // lo
__device__ __nv_bfloat16 g_wdh[C2*K3];   // deform weights, k=tap*256+ci, hi
__device__ __nv_bfloat16 g_wdl[C2*K3];   // lo

// -------- helpers --------
__device__ __forceinline__ uint32_t smem_u32(const void* p){
  uint32_t a;
  asm("{ .reg .u64 t; cvta.to.shared.u64 t, %1; cvt.u32.u64 %0, t; }" : "=r"(a) : "l"(p));
  return a;
}
#define SWZ(o) ((o) ^ (((o)>>3)&0x70))

__device__ __forceinline__ void ldsm4(uint32_t* r, uint32_t addr){
  asm volatile("ldmatrix.sync.aligned.m8n8.x4.shared.b16 {%0,%1,%2,%3}, [%4];"
    : "=r"(r[0]),"=r"(r[1]),"=r"(r[2]),"=r"(r[3]) : "r"(addr));
}
__device__ __forceinline__ void ldsm2(uint32_t* r, uint32_t addr){
  asm volatile("ldmatrix.sync.aligned.m8n8.x2.shared.b16 {%0,%1}, [%2];"
    : "=r"(r[0]),"=r"(r[1]) : "r"(addr));
}
__device__ __forceinline__ void mma16816(float* d, const uint32_t* a, const uint32_t* b){
  asm volatile("mma.sync.aligned.m16n8k16.row.col.f32.bf16.bf16.f32 "
    "{%0,%1,%2,%3}, {%4,%5,%6,%7}, {%8,%9}, {%0,%1,%2,%3};"
    : "+f"(d[0]), "+f"(d[1]), "+f"(d[2]), "+f"(d[3])
    : "r"(a[0]), "r"(a[1]), "r"(a[2]), "r"(a[3]), "r"(b[0]), "r"(b[1]));
}
__device__ __forceinline__ void cp_async16(uint32_t dst, const void* src){
  asm volatile("cp.async.cg.shared.global [%0], [%1], 16;" :: "r"(dst), "l"(src));
}
#define CP_COMMIT() asm volatile("cp.async.commit_group;" ::: "memory")
#define CP_WAIT0()  asm volatile("cp.async.wait_group 0;" ::: "memory")

__device__ __forceinline__ float silu_f(float v) {
  return __fdividef(v, 1.0f + __expf(-v));
}
__device__ __forceinline__ void split_bf16(float v, unsigned short& h, unsigned short& l){
  __nv_bfloat16 hh = __float2bfloat16(v);
  float hf = __bfloat162float(hh);
  __nv_bfloat16 ll = __float2bfloat16(v - hf);
  h = __bfloat16_as_ushort(hh);
  l = __bfloat16_as_ushort(ll);
}

// SMEM layout (byte offsets within dynamic smem)
// W buf[i]: 256 co-rows x 128B, hi 32K + lo 32K
#define SM_WB(i) ((i)*65536)
#define W_LO     32768
// P buf[i]: 64 px-rows x 128B, hi 8K + lo 8K
#define SM_PB(i) (131072 + (i)*16384)
#define P_LO     8192
#define SM_BN    163840   // scale[256] + shift[256]
#define SM_META  165888              // conv1: ih[64], iw[64]
#define SM_TOF   165888              // deform: t_off 9*64*16B = 9216
#define SM_TWT   175104              // deform: t_wt  9216
#define SMEM_CONV1  166912
#define SMEM_DEFORM 184320

// =====================================================================
// Prep: convert+reorder weights to bf16 hi/lo, k = tap*Cin + ci
// =====================================================================
__global__ void prep_kernel(const float* __restrict__ w1, const float* __restrict__ wd)
{
  int stride = gridDim.x * blockDim.x;
  for (int i = blockIdx.x*blockDim.x + threadIdx.x; i < C2*K1; i += stride) {
    int co = i / K1, t = i - co*K1, tap = t >> 7, ci = t & 127;
    float v = w1[(co*C1 + ci)*9 + tap];
    unsigned short h, l; split_bf16(v, h, l);
    g_w1h[i] = __ushort_as_bfloat16(h);
    g_w1l[i] = __ushort_as_bfloat16(l);
  }
  for (int i = blockIdx.x*blockDim.x + threadIdx.x; i < C2*K3; i += stride) {
    int co = i / K3, t = i - co*K3, tap = t >> 8, ci = t & 255;
    float v = wd[(co*C2 + ci)*9 + tap];
    unsigned short h, l; split_bf16(v, h, l);
    g_wdh[i] = __ushort_as_bfloat16(h);
    g_wdl[i] = __ushort_as_bfloat16(l);
  }
}

// =====================================================================
// One k16 step: warp tile 64co x 16px (mt=4, nt=2), 3-product hi/lo.
// 16 warps: 4 M-groups x 4 N-groups over 256co x 64px.
// =====================================================================
__device__ __forceinline__ void mma_kstep(uint32_t sb, uint32_t woff, uint32_t poff,
                                          int mrow0, int nrow0, int lane, int ks,
                                          float d[4][2][4])
{
  uint32_t bh[2][2], bl[2][2];
  const uint32_t bcol = ks*32 + ((lane >> 3) & 1) * 16;
  #pragma unroll
  for (int nt = 0; nt < 2; nt++) {
    uint32_t bo = SWZ((uint32_t)(nrow0 + nt*8 + (lane & 7)) * 128 + bcol);
    ldsm2(bh[nt], sb + poff + bo);
    ldsm2(bl[nt], sb + poff + P_LO + bo);
  }
  const uint32_t acol = ks*32 + ((lane >> 4) & 1) * 16;
  #pragma unroll
  for (int mt = 0; mt < 4; mt++) {
    uint32_t ah[4], al[4];
    uint32_t ao = SWZ((uint32_t)(mrow0 + mt*16 + (lane & 15)) * 128 + acol);
    ldsm4(ah, sb + woff + ao);
    ldsm4(al, sb + woff + W_LO + ao);
    #pragma unroll
    for (int nt = 0; nt < 2; nt++) {
      mma16816(d[mt][nt], ah, bh[nt]);
      mma16816(d[mt][nt], ah, bl[nt]);
      mma16816(d[mt][nt], al, bh[nt]);
    }
  }
}

// W chunk via cp.async: 256 rows x 64 k (hi+lo), 512 threads -> 8 cp each
__device__ __forceinline__ void cp_W(uint32_t sb, uint32_t woff,
    const __nv_bfloat16* wh, const __nv_bfloat16* wl, int K, int k0, int tid)
{
  #pragma unroll
  for (int i = 0; i < 4; i++) {
    int e = tid + i*512;              // 0..2047
    int row = e >> 3, col = e & 7;
    size_t sbyte = ((size_t)row * K + k0) * 2 + col * 16;
    uint32_t doff = SWZ((uint32_t)(row*128 + col*16));
    cp_async16(sb + woff + doff,        (const char*)wh + sbyte);
    cp_async16(sb + woff + W_LO + doff, (const char*)wl + sbyte);
  }
}

// deform: 16 corner loads for 4 ci planes
__device__ __forceinline__ void gath4(float* r, const float* base, int4 o4){
  #pragma unroll
  for (int j = 0; j < 4; j++) {
    const float* pp = base + (size_t)j * SPIX;
    r[j*4+0] = __ldg(pp + o4.x); r[j*4+1] = __ldg(pp + o4.y);
    r[j*4+2] = __ldg(pp + o4.z); r[j*4+3] = __ldg(pp + o4.w);
  }
}
// combine 4 ci + split + 8B stores; boff = byte offset of the 4-ci group in row
__device__ __forceinline__ void cons4(char* smem, uint32_t poff, const float* r,
                                      float4 w4, int p, int boff){
  unsigned short hs[4], ls[4];
  #pragma unroll
  for (int j = 0; j < 4; j++) {
    float v = w4.x*r[j*4+0] + w4.y*r[j*4+1] + w4.z*r[j*4+2] + w4.w*r[j*4+3];
    split_bf16(v, hs[j], ls[j]);
  }
  uint2 hv, lv;
  hv.x = (uint32_t)hs[0] | ((uint32_t)hs[1] << 16);
  hv.y = (uint32_t)hs[2] | ((uint32_t)hs[3] << 16);
  lv.x = (uint32_t)ls[0] | ((uint32_t)ls[1] << 16);
  lv.y = (uint32_t)ls[2] | ((uint32_t)ls[3] << 16);
  uint32_t doff = SWZ((uint32_t)(p*128 + boff));
  *(uint2*)(smem + poff + doff)        = hv;
  *(uint2*)(smem + poff + P_LO + doff) = lv;
}
// conv1: direct split of 4 raw values
__device__ __forceinline__ void cons4c(char* smem, uint32_t poff, const float* r,
                                       int p, int boff){
  unsigned short hs[4], ls[4];
  #pragma unroll
  for (int j = 0; j < 4; j++) split_bf16(r[j], hs[j], ls[j]);
  uint2 hv, lv;
  hv.x = (uint32_t)hs[0] | ((uint32_t)hs[1] << 16);
  hv.y = (uint32_t)hs[2] | ((uint32_t)hs[3] << 16);
  lv.x = (uint32_t)ls[0] | ((uint32_t)ls[1] << 16);
  lv.y = (uint32_t)ls[2] | ((uint32_t)ls[3] << 16);
  uint32_t doff = SWZ((uint32_t)(p*128 + boff));
  *(uint2*)(smem + poff + doff)        = hv;
  *(uint2*)(smem + poff + P_LO + doff) = lv;
}

// =====================================================================
// Kernel 1: conv3x3 s2 p1 (C1->C2) + BN1 + SiLU -> g_h (NCHW)
// CTA: 256 co x 64 px, 512 threads. 18 chunks of 64 (tap=c>>1).
// Pipelined: W cp.async double-buffer + gather interleaved with k-steps.
// =====================================================================
__global__ __launch_bounds__(512, 1)
void conv1_mma(const float* __restrict__ x,
               const float* __restrict__ bg, const float* __restrict__ bb,
               const float* __restrict__ bm, const float* __restrict__ bv)
{
  extern __shared__ char smem[];
  const uint32_t sb = smem_u32(smem);
  const int tid = threadIdx.x;
  const int n0 = blockIdx.x * PX;
  const int b  = n0 / SPIX;
  const int r0 = n0 - b * SPIX;

  if (tid < PX) {
    int r = r0 + tid, oh = r / HO, ow = r - oh * HO;
    ((int*)(smem + SM_META))[tid]       = 2*oh - 1;
    ((int*)(smem + SM_META + 256))[tid] = 2*ow - 1;
  }
  if (tid < 256) {
    float sc = bg[tid] * rsqrtf(bv[tid] + 1e-5f);
    ((float*)(smem + SM_BN))[tid]        = sc;
    ((float*)(smem + SM_BN + 1024))[tid] = bb[tid] - bm[tid] * sc;
  }
  __syncthreads();

  const int p   = tid & 63;    // gather pixel
  const int cig = tid >> 6;    // 0..7, 8 ci each
  const int ihb = ((int*)(smem + SM_META))[p];
  const int iwb = ((int*)(smem + SM_META + 256))[p];
  const float* xb = x + (size_t)b * C1 * HIN * HIN;

  const int lane = tid & 31, wid = tid >> 5;
  const int mrow0 = (wid >> 2) * 64;   // co
  const int nrow0 = (wid & 3) * 16;    // px

  float d[4][2][4];
  #pragma unroll
  for (int i = 0; i < 4; i++)
    #pragma unroll
    for (int j = 0; j < 2; j++)
      #pragma unroll
      for (int q = 0; q < 4; q++) d[i][j][q] = 0.0f;

  const int NC = 18;
  // ---- prologue: fill buf0 (tap 0, ci0 0) ----
  {
    const bool ok = ((unsigned)ihb < (unsigned)HIN) && ((unsigned)iwb < (unsigned)HIN);
    const float* src = xb + ihb*HIN + iwb + (size_t)(cig*8) * (HIN*HIN);
    #pragma unroll
    for (int g = 0; g < 2; g++) {
      float r4[4];
      #pragma unroll
      for (int j = 0; j < 4; j++)
        r4[j] = ok ? __ldg(src + (size_t)(g*4 + j) * (HIN*HIN)) : 0.0f;
      cons4c(smem, SM_PB(0), r4, p, cig*16 + g*8);
    }
    cp_W(sb, SM_WB(0), g_w1h, g_w1l, K1, 0, tid);
    CP_COMMIT(); CP_WAIT0();
  }
  __syncthreads();

  for (int c = 0; c < NC; c++) {
    const int buf = c & 1, nbuf = buf ^ 1;
    const uint32_t woff = SM_WB(buf), poff = SM_PB(buf);
    const bool pre = (c + 1 < NC);
    const float* srcn = nullptr; bool okn = false;
    if (pre) {
      cp_W(sb, SM_WB(nbuf), g_w1h, g_w1l, K1, (c+1)*64, tid);
      CP_COMMIT();
      const int cn = c + 1, tapn = cn >> 1, ci0n = (cn & 1) * 64;
      const int khn = tapn / 3, kwn = tapn - 3 * khn;
      const int ih = ihb + khn, iw = iwb + kwn;
      okn = ((unsigned)ih < (unsigned)HIN) && ((unsigned)iw < (unsigned)HIN);
      srcn = xb + ih*HIN + iw + (size_t)(ci0n + cig*8) * (HIN*HIN);
    }
    float rA[4], rB[4];
    if (pre) {
      #pragma unroll
      for (int j = 0; j < 4; j++) rA[j] = okn ? __ldg(srcn + (size_t)j*(HIN*HIN)) : 0.0f;
    }
    mma_kstep(sb, woff, poff, mrow0, nrow0, lane, 0, d);
    if (pre) {
      #pragma unroll
      for (int j = 0; j < 4; j++) rB[j] = okn ? __ldg(srcn + (size_t)(4+j)*(HIN*HIN)) : 0.0f;
    }
    mma_kstep(sb, woff, poff, mrow0, nrow0, lane, 1, d);
    if (pre) cons4c(smem, SM_PB(nbuf), rA, p, cig*16);
    mma_kstep(sb, woff, poff, mrow0, nrow0, lane, 2, d);
    if (pre) cons4c(smem, SM_PB(nbuf), rB, p, cig*16 + 8);
    mma_kstep(sb, woff, poff, mrow0, nrow0, lane, 3, d);
    CP_WAIT0();
    __syncthreads();
  }

  // ---- epilogue: BN1 + SiLU, float2 px-pair stores (NCHW) ----
  const float* s_sc = (const float*)(smem + SM_BN);
  const float* s_sh = (const float*)(smem + SM_BN + 1024);
  const int group = lane >> 2, tig = lane & 3;
  float* dst = g_h + (size_t)b * C2 * SPIX;
  #pragma unroll
  for (int mt = 0; mt < 4; mt++) {
    int ca = mrow0 + mt*16 + group, cb = ca + 8;
    float s0 = s_sc[ca], h0 = s_sh[ca];
    float s1 = s_sc[cb], h1 = s_sh[cb];
    #pragma unroll
    for (int nt = 0; nt < 2; nt++) {
      int px = r0 + nrow0 + nt*8 + tig*2;
      float2 v0 = make_float2(silu_f(fmaf(d[mt][nt][0], s0, h0)),
                              silu_f(fmaf(d[mt][nt][1], s0, h0)));
      float2 v1 = make_float2(silu_f(fmaf(d[mt][nt][2], s1, h1)),
                              silu_f(fmaf(d[mt][nt][3], s1, h1)));
      *(float2*)(dst + (size_t)ca * SPIX + px) = v0;
      *(float2*)(dst + (size_t)cb * SPIX + px) = v1;
    }
  }
}

// =====================================================================
// Kernel 2: offset conv3x3 s1 p1 (C2->18) + bias -> g_off (scalar f32x2)
// =====================================================================
__device__ __forceinline__ unsigned long long pack2(float v) {
  unsigned long long r;
  asm("mov.b64 %0, {%1, %1};" : "=l"(r) : "r"(__float_as_uint(v)));
  return r;
}
__device__ __forceinline__ void ffma2(unsigned long long &d, unsigned long long a,
                                      unsigned long long b) {
  asm("fma.rn.f32x2 %0, %1, %2, %0;" : "+l"(d) : "l"(a), "l"(b));
}
__device__ __forceinline__ float2 unpack2(unsigned long long v) {
  unsigned int lo, hi;
  asm("mov.b64 {%0, %1}, %2;" : "=r"(lo), "=r"(hi) : "l"(v));
  return make_float2(__uint_as_float(lo), __uint_as_float(hi));
}

__global__ __launch_bounds__(256)
void offs_kernel(const float* __restrict__ w, const float* __restrict__ bias)
{
  __shared__ __align__(16) float Ws[16][18];
  __shared__ __align__(16) float Xs[16][256];
  __shared__ int s_hb[256], s_ihb[256], s_iwb[256], s_r[256];

  const int tid = threadIdx.x;
  const int n0  = blockIdx.x * 256;
  {
    int n  = n0 + tid;
    int b  = n / SPIX;
    int r  = n - b * SPIX;
    int oh = r / HO, ow = r - oh * HO;
    s_hb [tid] = b * (C2 * SPIX);
    s_ihb[tid] = oh - 1;
    s_iwb[tid] = ow - 1;
    s_r  [tid] = b * (18 * SPIX) + r;
  }
  __syncthreads();
  const int my_hb = s_hb[tid], my_ihb = s_ihb[tid], my_iwb = s_iwb[tid];
  const int my_r  = s_r[tid];

  unsigned long long acc[9];
  #pragma unroll
  for (int i = 0; i < 9; i++) acc[i] = 0ull;

  for (int k0 = 0; k0 < K3; k0 += 16) {
    for (int e = tid; e < 18 * 16; e += 256) {
      int co = e >> 4, kk = e & 15;
      Ws[kk][co] = w[co * K3 + k0 + kk];
    }
    #pragma unroll 4
    for (int kk = 0; kk < 16; kk++) {
      int k  = k0 + kk;
      int ci = k / 9;
      int t  = k - ci * 9;
      int kh = t / 3, kw = t - kh * 3;
      int ih = my_ihb + kh, iw = my_iwb + kw;
      float val = 0.0f;
      if ((unsigned)ih < (unsigned)HO && (unsigned)iw < (unsigned)HO)
        val = g_h[my_hb + ci * SPIX + ih * HO + iw];
      Xs[kk][tid] = val;
    }
    __syncthreads();
    #pragma unroll
    for (int kk = 0; kk < 16; kk++) {
      unsigned long long xp = pack2(Xs[kk][tid]);
      const unsigned long long* wr = reinterpret_cast<const unsigned long long*>(&Ws[kk][0]);
      #pragma unroll
      for (int i = 0; i < 9; i++) ffma2(acc[i], wr[i], xp);
    }
    __syncthreads();
  }

  #pragma unroll
  for (int i = 0; i < 9; i++) {
    float2 v = unpack2(acc[i]);
    g_off[my_r + (2 * i    ) * SPIX] = v.x + bias[2 * i    ];
    g_off[my_r + (2 * i + 1) * SPIX] = v.y + bias[2 * i + 1];
  }
}

// =====================================================================
// Kernel 3: deformable conv3x3 + BN2 + SiLU -> out (NCHW)
// CTA: 256 co x 64 px, 512 threads. 36 chunks of 64 (tap=c>>2).
// Pipelined: gather batches interleaved with MMA k-steps; W via cp.async.
// =====================================================================
__global__ __launch_bounds__(512, 1)
void deform_mma(const float* __restrict__ bg, const float* __restrict__ bb,
                const float* __restrict__ bm, const float* __restrict__ bv,
                float* __restrict__ out)
{
  extern __shared__ char smem[];
  const uint32_t sb = smem_u32(smem);
  const int tid = threadIdx.x;
  const int n0 = blockIdx.x * PX;
  const int b  = n0 / SPIX;
  const int r0 = n0 - b * SPIX;

  if (tid < 256) {
    float sc = bg[tid] * rsqrtf(bv[tid] + 1e-5f);
    ((float*)(smem + SM_BN))[tid]        = sc;
    ((float*)(smem + SM_BN + 1024))[tid] = bb[tid] - bm[tid] * sc;
  }
  // bilinear corner tables per (tap, pixel)
  for (int e = tid; e < 9 * PX; e += 512) {
    int tap = e >> 6, p = e & 63;
    int r = r0 + p;
    int oh = r / HO, ow = r - oh * HO;
    int kh = tap / 3, kw = tap - 3 * kh;
    float dy = g_off[((size_t)b*18 + 2*tap    ) * SPIX + r];
    float dx = g_off[((size_t)b*18 + 2*tap + 1) * SPIX + r];
    float py = (float)(oh + kh - 1) + dy;
    float px = (float)(ow + kw - 1) + dx;
    float fy = floorf(py), fx = floorf(px);
    int   y0 = (int)fy,    x0 = (int)fx;
    float wy1 = py - fy, wx1 = px - fx;
    float wy0 = 1.0f - wy1, wx0 = 1.0f - wx1;
    int*   to = (int*)  (smem + SM_TOF + e*16);
    float* tw = (float*)(smem + SM_TWT + e*16);
    #pragma unroll
    for (int q = 0; q < 4; q++) {
      int yy = y0 + (q >> 1);
      int xx = x0 + (q & 1);
      float wq = ((q >> 1) ? wy1 : wy0) * ((q & 1) ? wx1 : wx0);
      bool okq = (yy >= 0) && (yy < HO) && (xx >= 0) && (xx < HO);
      int yc = min(max(yy, 0), HO - 1);
      int xc = min(max(xx, 0), HO - 1);
      to[q] = yc * HO + xc;
      tw[q] = okq ? wq : 0.0f;
    }
  }
  __syncthreads();

  const int p   = tid & 63;
  const int cig = tid >> 6;     // 0..7, 8 ci each
  const float* hbase = g_h + (size_t)b * C2 * SPIX;

  const int lane = tid & 31, wid = tid >> 5;
  const int mrow0 = (wid >> 2) * 64;
  const int nrow0 = (wid & 3) * 16;

  float d[4][2][4];
  #pragma unroll
  for (int i = 0; i < 4; i++)
    #pragma unroll
    for (int j = 0; j < 2; j++)
      #pragma unroll
      for (int q = 0; q < 4; q++) d[i][j][q] = 0.0f;

  const int NC = 36;
  // ---- prologue: fill buf0 (chunk 0: tap 0, ci0 0) ----
  {
    const int4   o4 = *(const int4*)  (smem + SM_TOF + (0*PX + p)*16);
    const float4 w4 = *(const float4*)(smem + SM_TWT + (0*PX + p)*16);
    const float* base = hbase + (size_t)(cig*8) * SPIX;
    #pragma unroll
    for (int g = 0; g < 2; g++) {
      float r16[16];
      gath4(r16, base + (size_t)(g*4) * SPIX, o4);
      cons4(smem, SM_PB(0), r16, w4, p, cig*16 + g*8);
    }
    cp_W(sb, SM_WB(0), g_wdh, g_wdl, K3, 0, tid);
    CP_COMMIT(); CP_WAIT0();
  }
  __syncthreads();

  for (int c = 0; c < NC; c++) {
    const int buf = c & 1, nbuf = buf ^ 1;
    const uint32_t woff = SM_WB(buf), poff = SM_PB(buf);
    const bool pre = (c + 1 < NC);
    int4 o4; float4 w4; const float* baseN = nullptr;
    if (pre) {
      cp_W(sb, SM_WB(nbuf), g_wdh, g_wdl, K3, (c+1)*64, tid);
      CP_COMMIT();
      const int cn = c + 1, tapn = cn >> 2, ci0n = (cn & 3) * 64;
      o4 = *(const int4*)  (smem + SM_TOF + (tapn*PX + p)*16);
      w4 = *(const float4*)(smem + SM_TWT + (tapn*PX + p)*16);
      baseN = hbase + (size_t)(ci0n + cig*8) * SPIX;
    }
    float rA[16], rB[16];
    if (pre) gath4(rA, baseN, o4);
    mma_kstep(sb, woff, poff, mrow0, nrow0, lane, 0, d);
    if (pre) gath4(rB, baseN + (size_t)4 * SPIX, o4);
    mma_kstep(sb, woff, poff, mrow0, nrow0, lane, 1, d);
    if (pre) cons4(smem, SM_PB(nbuf), rA, w4, p, cig*16);
    mma_kstep(sb, woff, poff, mrow0, nrow0, lane, 2, d);
    if (pre) cons4(smem, SM_PB(nbuf), rB, w4, p, cig*16 + 8);
    mma_kstep(sb, woff, poff, mrow0, nrow0, lane, 3, d);
    CP_WAIT0();
    __syncthreads();
  }

  // ---- epilogue: BN2 + SiLU, float2 px-pair stores (NCHW) ----
  const float* s_sc = (const float*)(smem + SM_BN);
  const float* s_sh = (const float*)(smem + SM_BN + 1024);
  const int group = lane >> 2, tig = lane & 3;
  float* dst = out + (size_t)b * C2 * SPIX;
  #pragma unroll
  for (int mt = 0; mt < 4; mt++) {
    int ca = mrow0 + mt*16 + group, cb = ca + 8;
    float s0 = s_sc[ca], h0 = s_sh[ca];
    float s1 = s_sc[cb], h1 = s_sh[cb];
    #pragma unroll
    for (int nt = 0; nt < 2; nt++) {
      int px = r0 + nrow0 + nt*8 + tig*2;
      float2 v0 = make_float2(silu_f(fmaf(d[mt][nt][0], s0, h0)),
                              silu_f(fmaf(d[mt][nt][1], s0, h0)));
      float2 v1 = make_float2(silu_f(fmaf(d[mt][nt][2], s1, h1)),
                              silu_f(fmaf(d[mt][nt][3], s1, h1)));
      *(float2*)(dst + (size_t)ca * SPIX + px) = v0;
      *(float2*)(dst + (size_t)cb * SPIX + px) = v1;
    }
  }
}

// =====================================================================
extern "C" void kernel_launch(void* const* d_in, const int* in_sizes, int n_in,
                              void* d_out, int out_size) {
  const float* x       = (const float*)d_in[0];
  const float* conv1_w = (const float*)d_in[1];
  const float* bn1_g   = (const float*)d_in[2];
  const float* bn1_b   = (const float*)d_in[3];
  const float* bn1_m   = (const float*)d_in[4];
  const float* bn1_v   = (const float*)d_in[5];
  const float* off_w   = (const float*)d_in[6];
  const float* off_b   = (const float*)d_in[7];
  const float* dconv_w = (const float*)d_in[8];
  const float* bn2_g   = (const float*)d_in[9];
  const float* bn2_b   = (const float*)d_in[10];
  const float* bn2_m   = (const float*)d_in[11];
  const float* bn2_v   = (const float*)d_in[12];
  float* out = (float*)d_out;

  cudaFuncSetAttribute(conv1_mma,  cudaFuncAttributeMaxDynamicSharedMemorySize, SMEM_CONV1);
  cudaFuncSetAttribute(deform_mma, cudaFuncAttributeMaxDynamicSharedMemorySize, SMEM_DEFORM);

  prep_kernel<<<512, 256>>>(conv1_w, dconv_w);
  conv1_mma<<<NPIX / PX, 512, SMEM_CONV1>>>(x, bn1_g, bn1_b, bn1_m, bn1_v);
  offs_kernel<<<NPIX / 256, 256>>>(off_w, off_b);
  deform_mma<<<NPIX / PX, 512, SMEM_DEFORM>>>(bn2_g, bn2_b, bn2_m, bn2_v, out);
}

// round 17
// speedup vs baseline: 1.4371x; 1.4371x over previous
#include <cuda_runtime.h>
#include <cuda_bf16.h>
#include <cstdint>

#define BATCH 8
#define C1    128
#define C2    256
#define HIN   160
#define HO    80
#define SPIX  6400
#define NPIX  51200
#define K1    1152
#define K3    2304

// -------- scratch (device globals; no runtime allocation) --------
__device__ float g_h  [BATCH*C2*SPIX];   // NCHW: [b][ci][pixel]
__device__ float g_off[BATCH*18*SPIX];   // offsets
__device__ __nv_bfloat16 g_w1h[C2*K1];   // conv1 weights, k=tap*128+ci, hi
__device__ __nv_bfloat16 g_w1l[C2*K1];   // lo
__device__ __nv_bfloat16 g_wdh[C2*K3];   // deform weights, k=tap*256+ci, hi
__device__ __nv_bfloat16 g_wdl[C2*K3];   // lo

// -------- helpers --------
__device__ __forceinline__ uint32_t smem_u32(const void* p){
  uint32_t a;
  asm("{ .reg .u64 t; cvta.to.shared.u64 t, %1; cvt.u32.u64 %0, t; }" : "=r"(a) : "l"(p));
  return a;
}
#define SWZ(o) ((o) ^ (((o)>>3)&0x70))

__device__ __forceinline__ void ldsm4(uint32_t* r, uint32_t addr){
  asm volatile("ldmatrix.sync.aligned.m8n8.x4.shared.b16 {%0,%1,%2,%3}, [%4];"
    : "=r"(r[0]),"=r"(r[1]),"=r"(r[2]),"=r"(r[3]) : "r"(addr));
}
__device__ __forceinline__ void ldsm2(uint32_t* r, uint32_t addr){
  asm volatile("ldmatrix.sync.aligned.m8n8.x2.shared.b16 {%0,%1}, [%2];"
    : "=r"(r[0]),"=r"(r[1]) : "r"(addr));
}
__device__ __forceinline__ void mma16816(float* d, const uint32_t* a, const uint32_t* b){
  asm volatile("mma.sync.aligned.m16n8k16.row.col.f32.bf16.bf16.f32 "
    "{%0,%1,%2,%3}, {%4,%5,%6,%7}, {%8,%9}, {%0,%1,%2,%3};"
    : "+f"(d[0]), "+f"(d[1]), "+f"(d[2]), "+f"(d[3])
    : "r"(a[0]), "r"(a[1]), "r"(a[2]), "r"(a[3]), "r"(b[0]), "r"(b[1]));
}
__device__ __forceinline__ void cp_async16(uint32_t dst, const void* src){
  asm volatile("cp.async.cg.shared.global [%0], [%1], 16;" :: "r"(dst), "l"(src));
}
#define CP_COMMIT() asm volatile("cp.async.commit_group;" ::: "memory")
#define CP_WAIT0()  asm volatile("cp.async.wait_group 0;" ::: "memory")

__device__ __forceinline__ float silu_f(float v) {
  return __fdividef(v, 1.0f + __expf(-v));
}
__device__ __forceinline__ void split_bf16(float v, unsigned short& h, unsigned short& l){
  __nv_bfloat16 hh = __float2bfloat16(v);
  float hf = __bfloat162float(hh);
  __nv_bfloat16 ll = __float2bfloat16(v - hf);
  h = __bfloat16_as_ushort(hh);
  l = __bfloat16_as_ushort(ll);
}

// SMEM layout (byte offsets within dynamic smem)
// W buf[i]: 256 co-rows x 128B, hi 32K + lo 32K
#define SM_WB(i) ((i)*65536)
#define W_LO     32768
// P buf[i]: 128 px-rows x 128B, hi 16K + lo 16K
#define SM_PB(i) (131072 + (i)*32768)
#define P_LO     16384
#define SM_BN    196608   // scale[256] + shift[256] (2KB)
#define SM_TB    198656   // conv1: ih[128] iw[128] (1KB) | deform: 9*128*16B (18KB)
#define SMEM_CONV1  199680
#define SMEM_DEFORM 217088

// =====================================================================
// Prep: convert+reorder weights to bf16 hi/lo, k = tap*Cin + ci
// =====================================================================
__global__ void prep_kernel(const float* __restrict__ w1, const float* __restrict__ wd)
{
  int stride = gridDim.x * blockDim.x;
  for (int i = blockIdx.x*blockDim.x + threadIdx.x; i < C2*K1; i += stride) {
    int co = i / K1, t = i - co*K1, tap = t >> 7, ci = t & 127;
    float v = w1[(co*C1 + ci)*9 + tap];
    unsigned short h, l; split_bf16(v, h, l);
    g_w1h[i] = __ushort_as_bfloat16(h);
    g_w1l[i] = __ushort_as_bfloat16(l);
  }
  for (int i = blockIdx.x*blockDim.x + threadIdx.x; i < C2*K3; i += stride) {
    int co = i / K3, t = i - co*K3, tap = t >> 8, ci = t & 255;
    float v = wd[(co*C2 + ci)*9 + tap];
    unsigned short h, l; split_bf16(v, h, l);
    g_wdh[i] = __ushort_as_bfloat16(h);
    g_wdl[i] = __ushort_as_bfloat16(l);
  }
}

// =====================================================================
// One k16 step of the R7 warp tile: 64co x 32px (mt=4, nt=4), 3-product.
// 16 warps: 4(M) x 4(N) covering 256co x 128px.
// =====================================================================
__device__ __forceinline__ void mma_kstep(uint32_t sb, uint32_t woff, uint32_t poff,
                                          int mrow0, int nrow0, int lane, int ks,
                                          float d[4][4][4])
{
  uint32_t bh[4][2], bl[4][2];
  const uint32_t bcol = ks*32 + ((lane >> 3) & 1) * 16;
  #pragma unroll
  for (int nt = 0; nt < 4; nt++) {
    uint32_t bo = SWZ((uint32_t)(nrow0 + nt*8 + (lane & 7)) * 128 + bcol);
    ldsm2(bh[nt], sb + poff + bo);
    ldsm2(bl[nt], sb + poff + P_LO + bo);
  }
  const uint32_t acol = ks*32 + ((lane >> 4) & 1) * 16;
  #pragma unroll
  for (int mt = 0; mt < 4; mt++) {
    uint32_t ah[4], al[4];
    uint32_t ao = SWZ((uint32_t)(mrow0 + mt*16 + (lane & 15)) * 128 + acol);
    ldsm4(ah, sb + woff + ao);
    ldsm4(al, sb + woff + W_LO + ao);
    #pragma unroll
    for (int nt = 0; nt < 4; nt++) {
      mma16816(d[mt][nt], ah, bh[nt]);
      mma16816(d[mt][nt], ah, bl[nt]);
      mma16816(d[mt][nt], al, bh[nt]);
    }
  }
}

// W chunk via cp.async: 256 rows x 64 k (hi+lo), 512 threads
__device__ __forceinline__ void cp_W(uint32_t sb, uint32_t woff,
    const __nv_bfloat16* wh, const __nv_bfloat16* wl, int K, int k0, int tid)
{
  #pragma unroll
  for (int i = 0; i < 4; i++) {
    int e = tid + i*512;              // 0..2047
    int row = e >> 3, col = e & 7;
    size_t sbyte = ((size_t)row * K + k0) * 2 + col * 16;
    uint32_t doff = SWZ((uint32_t)(row*128 + col*16));
    cp_async16(sb + woff + doff,        (const char*)wh + sbyte);
    cp_async16(sb + woff + W_LO + doff, (const char*)wl + sbyte);
  }
}

// deform: 8 corner loads for 2 ci planes
__device__ __forceinline__ void gath2(float* r, const float* base, int4 o4){
  #pragma unroll
  for (int j = 0; j < 2; j++) {
    const float* pp = base + (size_t)j * SPIX;
    r[j*4+0] = __ldg(pp + o4.x); r[j*4+1] = __ldg(pp + o4.y);
    r[j*4+2] = __ldg(pp + o4.z); r[j*4+3] = __ldg(pp + o4.w);
  }
}
// combine 2 ci + split + 4B stores; boff = byte offset within row
__device__ __forceinline__ void cons2(char* smem, uint32_t poff, const float* r,
                                      float4 w4, int p, int boff){
  unsigned short hs[2], ls[2];
  #pragma unroll
  for (int j = 0; j < 2; j++) {
    float v = w4.x*r[j*4+0] + w4.y*r[j*4+1] + w4.z*r[j*4+2] + w4.w*r[j*4+3];
    split_bf16(v, hs[j], ls[j]);
  }
  uint32_t hv = (uint32_t)hs[0] | ((uint32_t)hs[1] << 16);
  uint32_t lv = (uint32_t)ls[0] | ((uint32_t)ls[1] << 16);
  uint32_t doff = SWZ((uint32_t)(p*128 + boff));
  *(uint32_t*)(smem + poff + doff)        = hv;
  *(uint32_t*)(smem + poff + P_LO + doff) = lv;
}
// conv1: direct split of 4 raw values, 8B stores
__device__ __forceinline__ void cons4c(char* smem, uint32_t poff, const float* r,
                                       int p, int boff){
  unsigned short hs[4], ls[4];
  #pragma unroll
  for (int j = 0; j < 4; j++) split_bf16(r[j], hs[j], ls[j]);
  uint2 hv, lv;
  hv.x = (uint32_t)hs[0] | ((uint32_t)hs[1] << 16);
  hv.y = (uint32_t)hs[2] | ((uint32_t)hs[3] << 16);
  lv.x = (uint32_t)ls[0] | ((uint32_t)ls[1] << 16);
  lv.y = (uint32_t)ls[2] | ((uint32_t)ls[3] << 16);
  uint32_t doff = SWZ((uint32_t)(p*128 + boff));
  *(uint2*)(smem + poff + doff)        = hv;
  *(uint2*)(smem + poff + P_LO + doff) = lv;
}

// =====================================================================
// Kernel 1: conv3x3 s2 p1 (C1->C2) + BN1 + SiLU -> g_h (NCHW)
// CTA: 256 co x 128 px, 512 threads (R7 shape). 18 chunks of 64.
// W double-buffered cp.async; im2col loads interleaved with k-steps.
// =====================================================================
__global__ __launch_bounds__(512, 1)
void conv1_mma(const float* __restrict__ x,
               const float* __restrict__ bg, const float* __restrict__ bb,
               const float* __restrict__ bm, const float* __restrict__ bv)
{
  extern __shared__ char smem[];
  const uint32_t sb = smem_u32(smem);
  const int tid = threadIdx.x;
  const int n0 = blockIdx.x * 128;
  const int b  = n0 / SPIX;
  const int r0 = n0 - b * SPIX;

  if (tid < 128) {
    int r = r0 + tid, oh = r / HO, ow = r - oh * HO;
    ((int*)(smem + SM_TB))[tid]       = 2*oh - 1;
    ((int*)(smem + SM_TB + 512))[tid] = 2*ow - 1;
  }
  if (tid < 256) {
    float sc = bg[tid] * rsqrtf(bv[tid] + 1e-5f);
    ((float*)(smem + SM_BN))[tid]        = sc;
    ((float*)(smem + SM_BN + 1024))[tid] = bb[tid] - bm[tid] * sc;
  }
  __syncthreads();

  const int p   = tid & 127;
  const int cig = tid >> 7;    // 0..3, 16 ci each
  const int ihb = ((int*)(smem + SM_TB))[p];
  const int iwb = ((int*)(smem + SM_TB + 512))[p];
  const float* xb = x + (size_t)b * C1 * HIN * HIN;

  const int lane = tid & 31, wid = tid >> 5;
  const int mrow0 = (wid >> 2) * 64;   // co
  const int nrow0 = (wid & 3) * 32;    // px

  float d[4][4][4];
  #pragma unroll
  for (int i = 0; i < 4; i++)
    #pragma unroll
    for (int j = 0; j < 4; j++)
      #pragma unroll
      for (int q = 0; q < 4; q++) d[i][j][q] = 0.0f;

  const int NC = 18;
  // ---- prologue: fill PB(0) (tap 0, ci0 0), W(0) via cp.async ----
  {
    const bool ok = ((unsigned)ihb < (unsigned)HIN) && ((unsigned)iwb < (unsigned)HIN);
    const float* src = xb + ihb*HIN + iwb + (size_t)(cig*16) * (HIN*HIN);
    #pragma unroll
    for (int g = 0; g < 4; g++) {
      float r4[4];
      #pragma unroll
      for (int j = 0; j < 4; j++)
        r4[j] = ok ? __ldg(src + (size_t)(g*4 + j) * (HIN*HIN)) : 0.0f;
      cons4c(smem, SM_PB(0), r4, p, cig*32 + g*8);
    }
    cp_W(sb, SM_WB(0), g_w1h, g_w1l, K1, 0, tid);
    CP_COMMIT(); CP_WAIT0();
  }
  __syncthreads();

  for (int c = 0; c < NC; c++) {
    const int buf = c & 1, nbuf = buf ^ 1;
    const uint32_t woff = SM_WB(buf), poff = SM_PB(buf);
    const bool pre = (c + 1 < NC);
    const float* srcn = nullptr; bool okn = false;
    if (pre) {
      cp_W(sb, SM_WB(nbuf), g_w1h, g_w1l, K1, (c+1)*64, tid);
      CP_COMMIT();
      const int cn = c + 1, tapn = cn >> 1, ci0n = (cn & 1) * 64;
      const int khn = tapn / 3, kwn = tapn - 3 * khn;
      const int ih = ihb + khn, iw = iwb + kwn;
      okn = ((unsigned)ih < (unsigned)HIN) && ((unsigned)iw < (unsigned)HIN);
      srcn = xb + ih*HIN + iw + (size_t)(ci0n + cig*16) * (HIN*HIN);
    }
    float rA[4], rB[4];
    if (pre) {
      #pragma unroll
      for (int j = 0; j < 4; j++) rA[j] = okn ? __ldg(srcn + (size_t)j*(HIN*HIN)) : 0.0f;
      #pragma unroll
      for (int j = 0; j < 4; j++) rB[j] = okn ? __ldg(srcn + (size_t)(4+j)*(HIN*HIN)) : 0.0f;
    }
    mma_kstep(sb, woff, poff, mrow0, nrow0, lane, 0, d);
    if (pre) {
      cons4c(smem, SM_PB(nbuf), rA, p, cig*32);
      #pragma unroll
      for (int j = 0; j < 4; j++) rA[j] = okn ? __ldg(srcn + (size_t)(8+j)*(HIN*HIN)) : 0.0f;
    }
    mma_kstep(sb, woff, poff, mrow0, nrow0, lane, 1, d);
    if (pre) {
      cons4c(smem, SM_PB(nbuf), rB, p, cig*32 + 8);
      #pragma unroll
      for (int j = 0; j < 4; j++) rB[j] = okn ? __ldg(srcn + (size_t)(12+j)*(HIN*HIN)) : 0.0f;
    }
    mma_kstep(sb, woff, poff, mrow0, nrow0, lane, 2, d);
    if (pre) cons4c(smem, SM_PB(nbuf), rA, p, cig*32 + 16);
    mma_kstep(sb, woff, poff, mrow0, nrow0, lane, 3, d);
    if (pre) cons4c(smem, SM_PB(nbuf), rB, p, cig*32 + 24);
    CP_WAIT0();
    __syncthreads();
  }

  // ---- epilogue: BN1 + SiLU, float2 px-pair stores (NCHW) ----
  const float* s_sc = (const float*)(smem + SM_BN);
  const float* s_sh = (const float*)(smem + SM_BN + 1024);
  const int group = lane >> 2, tig = lane & 3;
  float* dst = g_h + (size_t)b * C2 * SPIX;
  #pragma unroll
  for (int mt = 0; mt < 4; mt++) {
    int ca = mrow0 + mt*16 + group, cb = ca + 8;
    float s0 = s_sc[ca], h0 = s_sh[ca];
    float s1 = s_sc[cb], h1 = s_sh[cb];
    #pragma unroll
    for (int nt = 0; nt < 4; nt++) {
      int px = r0 + nrow0 + nt*8 + tig*2;
      float2 v0 = make_float2(silu_f(fmaf(d[mt][nt][0], s0, h0)),
                              silu_f(fmaf(d[mt][nt][1], s0, h0)));
      float2 v1 = make_float2(silu_f(fmaf(d[mt][nt][2], s1, h1)),
                              silu_f(fmaf(d[mt][nt][3], s1, h1)));
      *(float2*)(dst + (size_t)ca * SPIX + px) = v0;
      *(float2*)(dst + (size_t)cb * SPIX + px) = v1;
    }
  }
}

// =====================================================================
// Kernel 2: offset conv3x3 s1 p1 (C2->18) + bias -> g_off (scalar f32x2)
// =====================================================================
__device__ __forceinline__ unsigned long long pack2(float v) {
  unsigned long long r;
  asm("mov.b64 %0, {%1, %1};" : "=l"(r) : "r"(__float_as_uint(v)));
  return r;
}
__device__ __forceinline__ void ffma2(unsigned long long &d, unsigned long long a,
                                      unsigned long long b) {
  asm("fma.rn.f32x2 %0, %1, %2, %0;" : "+l"(d) : "l"(a), "l"(b));
}
__device__ __forceinline__ float2 unpack2(unsigned long long v) {
  unsigned int lo, hi;
  asm("mov.b64 {%0, %1}, %2;" : "=r"(lo), "=r"(hi) : "l"(v));
  return make_float2(__uint_as_float(lo), __uint_as_float(hi));
}

__global__ __launch_bounds__(256)
void offs_kernel(const float* __restrict__ w, const float* __restrict__ bias)
{
  __shared__ __align__(16) float Ws[16][18];
  __shared__ __align__(16) float Xs[16][256];
  __shared__ int s_hb[256], s_ihb[256], s_iwb[256], s_r[256];

  const int tid = threadIdx.x;
  const int n0  = blockIdx.x * 256;
  {
    int n  = n0 + tid;
    int b  = n / SPIX;
    int r  = n - b * SPIX;
    int oh = r / HO, ow = r - oh * HO;
    s_hb [tid] = b * (C2 * SPIX);
    s_ihb[tid] = oh - 1;
    s_iwb[tid] = ow - 1;
    s_r  [tid] = b * (18 * SPIX) + r;
  }
  __syncthreads();
  const int my_hb = s_hb[tid], my_ihb = s_ihb[tid], my_iwb = s_iwb[tid];
  const int my_r  = s_r[tid];

  unsigned long long acc[9];
  #pragma unroll
  for (int i = 0; i < 9; i++) acc[i] = 0ull;

  for (int k0 = 0; k0 < K3; k0 += 16) {
    for (int e = tid; e < 18 * 16; e += 256) {
      int co = e >> 4, kk = e & 15;
      Ws[kk][co] = w[co * K3 + k0 + kk];
    }
    #pragma unroll 4
    for (int kk = 0; kk < 16; kk++) {
      int k  = k0 + kk;
      int ci = k / 9;
      int t  = k - ci * 9;
      int kh = t / 3, kw = t - kh * 3;
      int ih = my_ihb + kh, iw = my_iwb + kw;
      float val = 0.0f;
      if ((unsigned)ih < (unsigned)HO && (unsigned)iw < (unsigned)HO)
        val = g_h[my_hb + ci * SPIX + ih * HO + iw];
      Xs[kk][tid] = val;
    }
    __syncthreads();
    #pragma unroll
    for (int kk = 0; kk < 16; kk++) {
      unsigned long long xp = pack2(Xs[kk][tid]);
      const unsigned long long* wr = reinterpret_cast<const unsigned long long*>(&Ws[kk][0]);
      #pragma unroll
      for (int i = 0; i < 9; i++) ffma2(acc[i], wr[i], xp);
    }
    __syncthreads();
  }

  #pragma unroll
  for (int i = 0; i < 9; i++) {
    float2 v = unpack2(acc[i]);
    g_off[my_r + (2 * i    ) * SPIX] = v.x + bias[2 * i    ];
    g_off[my_r + (2 * i + 1) * SPIX] = v.y + bias[2 * i + 1];
  }
}

// =====================================================================
// Kernel 3: deformable conv3x3 + BN2 + SiLU -> out (NCHW)
// CTA: 256 co x 128 px, 512 threads (R7 shape). 36 chunks of 64.
// W double-buffered cp.async; bilinear gather interleaved in 2-ci batches.
// Compressed tables: {y0,x0,wy1,wx1} per (tap,px), corners re-derived.
// =====================================================================
__global__ __launch_bounds__(512, 1)
void deform_mma(const float* __restrict__ bg, const float* __restrict__ bb,
                const float* __restrict__ bm, const float* __restrict__ bv,
                float* __restrict__ out)
{
  extern __shared__ char smem[];
  const uint32_t sb = smem_u32(smem);
  const int tid = threadIdx.x;
  const int n0 = blockIdx.x * 128;
  const int b  = n0 / SPIX;
  const int r0 = n0 - b * SPIX;

  if (tid < 256) {
    float sc = bg[tid] * rsqrtf(bv[tid] + 1e-5f);
    ((float*)(smem + SM_BN))[tid]        = sc;
    ((float*)(smem + SM_BN + 1024))[tid] = bb[tid] - bm[tid] * sc;
  }
  // compressed bilinear tables per (tap, pixel): {y0, x0, wy1, wx1}
  for (int e = tid; e < 9 * 128; e += 512) {
    int tap = e >> 7, p = e & 127;
    int r = r0 + p;
    int oh = r / HO, ow = r - oh * HO;
    int kh = tap / 3, kw = tap - 3 * kh;
    float dy = g_off[((size_t)b*18 + 2*tap    ) * SPIX + r];
    float dx = g_off[((size_t)b*18 + 2*tap + 1) * SPIX + r];
    float py = (float)(oh + kh - 1) + dy;
    float px = (float)(ow + kw - 1) + dx;
    float fy = floorf(py), fx = floorf(px);
    int* tb = (int*)(smem + SM_TB + e*16);
    tb[0] = (int)fy;
    tb[1] = (int)fx;
    tb[2] = __float_as_int(py - fy);
    tb[3] = __float_as_int(px - fx);
  }
  __syncthreads();

  const int p   = tid & 127;
  const int cig = tid >> 7;     // 0..3, 16 ci each
  const float* hbase = g_h + (size_t)b * C2 * SPIX;

  const int lane = tid & 31, wid = tid >> 5;
  const int mrow0 = (wid >> 2) * 64;
  const int nrow0 = (wid & 3) * 32;

  float d[4][4][4];
  #pragma unroll
  for (int i = 0; i < 4; i++)
    #pragma unroll
    for (int j = 0; j < 4; j++)
      #pragma unroll
      for (int q = 0; q < 4; q++) d[i][j][q] = 0.0f;

  // derive corners for a tap
  auto derive = [&](int tap, int4& o4, float4& w4) {
    const int4 tb = *(const int4*)(smem + SM_TB + (tap*128 + p)*16);
    const int y0 = tb.x, x0 = tb.y;
    const float wy1 = __int_as_float(tb.z), wx1 = __int_as_float(tb.w);
    const float wy0 = 1.0f - wy1, wx0 = 1.0f - wx1;
    int   oo[4]; float ww[4];
    #pragma unroll
    for (int q = 0; q < 4; q++) {
      int yy = y0 + (q >> 1);
      int xx = x0 + (q & 1);
      bool ok = (yy >= 0) && (yy < HO) && (xx >= 0) && (xx < HO);
      int yc = min(max(yy, 0), HO - 1);
      int xc = min(max(xx, 0), HO - 1);
      oo[q] = yc * HO + xc;
      ww[q] = ok ? ((q >> 1) ? wy1 : wy0) * ((q & 1) ? wx1 : wx0) : 0.0f;
    }
    o4 = make_int4(oo[0], oo[1], oo[2], oo[3]);
    w4 = make_float4(ww[0], ww[1], ww[2], ww[3]);
  };

  const int NC = 36;
  // ---- prologue: fill PB(0) (chunk 0: tap 0, ci0 0), W(0) cp.async ----
  {
    int4 o4; float4 w4;
    derive(0, o4, w4);
    const float* base = hbase + (size_t)(cig*16) * SPIX;
    #pragma unroll
    for (int g = 0; g < 8; g++) {
      float r8[8];
      gath2(r8, base + (size_t)(g*2) * SPIX, o4);
      cons2(smem, SM_PB(0), r8, w4, p, cig*32 + g*4);
    }
    cp_W(sb, SM_WB(0), g_wdh, g_wdl, K3, 0, tid);
    CP_COMMIT(); CP_WAIT0();
  }
  __syncthreads();

  for (int c = 0; c < NC; c++) {
    const int buf = c & 1, nbuf = buf ^ 1;
    const uint32_t woff = SM_WB(buf), poff = SM_PB(buf);
    const bool pre = (c + 1 < NC);
    int4 o4; float4 w4; const float* baseN = nullptr;
    if (pre) {
      cp_W(sb, SM_WB(nbuf), g_wdh, g_wdl, K3, (c+1)*64, tid);
      CP_COMMIT();
      const int cn = c + 1, tapn = cn >> 2, ci0n = (cn & 3) * 64;
      derive(tapn, o4, w4);
      baseN = hbase + (size_t)(ci0n + cig*16) * SPIX;
    }
    float rA[8], rB[8];
    if (pre) {
      gath2(rA, baseN, o4);                          // b0: ci 0,1
      gath2(rB, baseN + (size_t)2 * SPIX, o4);       // b1: ci 2,3
    }
    mma_kstep(sb, woff, poff, mrow0, nrow0, lane, 0, d);
    if (pre) {
      cons2(smem, SM_PB(nbuf), rA, w4, p, cig*32 + 0*4);
      gath2(rA, baseN + (size_t)4 * SPIX, o4);       // b2
      cons2(smem, SM_PB(nbuf), rB, w4, p, cig*32 + 1*4);
      gath2(rB, baseN + (size_t)6 * SPIX, o4);       // b3
    }
    mma_kstep(sb, woff, poff, mrow0, nrow0, lane, 1, d);
    if (pre) {
      cons2(smem, SM_PB(nbuf), rA, w4, p, cig*32 + 2*4);
      gath2(rA, baseN + (size_t)8 * SPIX, o4);       // b4
      cons2(smem, SM_PB(nbuf), rB, w4, p, cig*32 + 3*4);
      gath2(rB, baseN + (size_t)10 * SPIX, o4);      // b5
    }
    mma_kstep(sb, woff, poff, mrow0, nrow0, lane, 2, d);
    if (pre) {
      cons2(smem, SM_PB(nbuf), rA, w4, p, cig*32 + 4*4);
      gath2(rA, baseN + (size_t)12 * SPIX, o4);      // b6
      cons2(smem, SM_PB(nbuf), rB, w4, p, cig*32 + 5*4);
      gath2(rB, baseN + (size_t)14 * SPIX, o4);      // b7
    }
    mma_kstep(sb, woff, poff, mrow0, nrow0, lane, 3, d);
    if (pre) {
      cons2(smem, SM_PB(nbuf), rA, w4, p, cig*32 + 6*4);
      cons2(smem, SM_PB(nbuf), rB, w4, p, cig*32 + 7*4);
    }
    CP_WAIT0();
    __syncthreads();
  }

  // ---- epilogue: BN2 + SiLU, float2 px-pair stores (NCHW) ----
  const float* s_sc = (const float*)(smem + SM_BN);
  const float* s_sh = (const float*)(smem + SM_BN + 1024);
  const int group = lane >> 2, tig = lane & 3;
  float* dst = out + (size_t)b * C2 * SPIX;
  #pragma unroll
  for (int mt = 0; mt < 4; mt++) {
    int ca = mrow0 + mt*16 + group, cb = ca + 8;
    float s0 = s_sc[ca], h0 = s_sh[ca];
    float s1 = s_sc[cb], h1 = s_sh[cb];
    #pragma unroll
    for (int nt = 0; nt < 4; nt++) {
      int px = r0 + nrow0 + nt*8 + tig*2;
      float2 v0 = make_float2(silu_f(fmaf(d[mt][nt][0], s0, h0)),
                              silu_f(fmaf(d[mt][nt][1], s0, h0)));
      float2 v1 = make_float2(silu_f(fmaf(d[mt][nt][2], s1, h1)),
                              silu_f(fmaf(d[mt][nt][3], s1, h1)));
      *(float2*)(dst + (size_t)ca * SPIX + px) = v0;
      *(float2*)(dst + (size_t)cb * SPIX + px) = v1;
    }
  }
}

// =====================================================================
extern "C" void kernel_launch(void* const* d_in, const int* in_sizes, int n_in,
                              void* d_out, int out_size) {
  const float* x       = (const float*)d_in[0];
  const float* conv1_w = (const float*)d_in[1];
  const float* bn1_g   = (const float*)d_in[2];
  const float* bn1_b   = (const float*)d_in[3];
  const float* bn1_m   = (const float*)d_in[4];
  const float* bn1_v   = (const float*)d_in[5];
  const float* off_w   = (const float*)d_in[6];
  const float* off_b   = (const float*)d_in[7];
  const float* dconv_w = (const float*)d_in[8];
  const float* bn2_g   = (const float*)d_in[9];
  const float* bn2_b   = (const float*)d_in[10];
  const float* bn2_m   = (const float*)d_in[11];
  const float* bn2_v   = (const float*)d_in[12];
  float* out = (float*)d_out;

  cudaFuncSetAttribute(conv1_mma,  cudaFuncAttributeMaxDynamicSharedMemorySize, SMEM_CONV1);
  cudaFuncSetAttribute(deform_mma, cudaFuncAttributeMaxDynamicSharedMemorySize, SMEM_DEFORM);

  prep_kernel<<<512, 256>>>(conv1_w, dconv_w);
  conv1_mma<<<NPIX / 128, 512, SMEM_CONV1>>>(x, bn1_g, bn1_b, bn1_m, bn1_v);
  offs_kernel<<<NPIX / 256, 256>>>(off_w, off_b);
  deform_mma<<<NPIX / 128, 512, SMEM_DEFORM>>>(bn2_g, bn2_b, bn2_m, bn2_v, out);
}